// round 2
// baseline (speedup 1.0000x reference)
#include <cuda_runtime.h>
#include <cuda_bf16.h>
#include <math.h>

// Problem constants
#define BB 4096
#define DD 256
#define HH 512
#define TT 45
#define N4H 2048

// GEMM tile config
#define BM 128
#define BN 64
#define BK 16

// Scratch (no allocations allowed -> __device__ globals)
__device__ float g_H0[BB * HH];
__device__ float g_C0[BB * HH];
__device__ float g_H1[BB * HH];
__device__ float g_C1[BB * HH];
__device__ float g_Xc[BB * N4H];
__device__ float g_G [BB * N4H];
__device__ float g_intent[BB];

// ---------------------------------------------------------------------------
// Fused GEMM: C[m,n] = sum_k A0[m,k]*B0[k,n]  (+ sum_k A1[m,k]*B1[k,n])
//                      + bias0[n] + bias1[n] + Xadd[m,n] + intent[m]*wrow[n]
// All optional parts controlled by null pointers. M = gridDim.y*BM,
// N = gridDim.x*BN. Requires M%128==0, N%64==0, K%16==0, 16B alignment.
// ---------------------------------------------------------------------------
__global__ __launch_bounds__(256, 2)
void gemm_fused(const float* __restrict__ A0, int lda0,
                const float* __restrict__ B0, int ldb0, int K0,
                const float* __restrict__ A1, int lda1,
                const float* __restrict__ B1, int ldb1, int K1,
                const float* __restrict__ bias0,
                const float* __restrict__ bias1,
                const float* __restrict__ Xadd,
                const float* __restrict__ intent,
                const float* __restrict__ wrow,
                float* __restrict__ C, int ldc)
{
    __shared__ float As[BK][BM + 4];
    __shared__ float Bs[BK][BN];

    const int tid = threadIdx.x;
    const int tx  = tid & 15;   // n direction (x4)
    const int ty  = tid >> 4;   // m direction (x8)
    const int m0  = blockIdx.y * BM;
    const int n0  = blockIdx.x * BN;

    float acc[8][4];
    #pragma unroll
    for (int i = 0; i < 8; ++i)
        #pragma unroll
        for (int j = 0; j < 4; ++j) acc[i][j] = 0.f;

    #pragma unroll 1
    for (int s = 0; s < 2; ++s) {
        const float* A = (s == 0) ? A0 : A1;
        if (A == nullptr) break;
        const float* Bp = (s == 0) ? B0 : B1;
        const int lda = (s == 0) ? lda0 : lda1;
        const int ldb = (s == 0) ? ldb0 : ldb1;
        const int K   = (s == 0) ? K0  : K1;

        const int arow = tid >> 2;          // 0..63
        const int akc  = (tid & 3) * 4;     // 0,4,8,12
        const int brow = tid >> 4;          // 0..15
        const int bnc  = (tid & 15) * 4;    // 0..60

        #pragma unroll 1
        for (int k0 = 0; k0 < K; k0 += BK) {
            // A tile 128x16 -> As[k][m] (transposed)
            #pragma unroll
            for (int p = 0; p < 2; ++p) {
                int r = arow + p * 64;
                float4 v = *(const float4*)(A + (size_t)(m0 + r) * lda + k0 + akc);
                As[akc + 0][r] = v.x;
                As[akc + 1][r] = v.y;
                As[akc + 2][r] = v.z;
                As[akc + 3][r] = v.w;
            }
            // B tile 16x64
            {
                float4 v = *(const float4*)(Bp + (size_t)(k0 + brow) * ldb + n0 + bnc);
                *(float4*)&Bs[brow][bnc] = v;
            }
            __syncthreads();

            #pragma unroll
            for (int kk = 0; kk < BK; ++kk) {
                float a[8], b[4];
                *(float4*)&a[0] = *(const float4*)&As[kk][ty * 8];
                *(float4*)&a[4] = *(const float4*)&As[kk][ty * 8 + 4];
                *(float4*)&b[0] = *(const float4*)&Bs[kk][tx * 4];
                #pragma unroll
                for (int i = 0; i < 8; ++i)
                    #pragma unroll
                    for (int j = 0; j < 4; ++j)
                        acc[i][j] = fmaf(a[i], b[j], acc[i][j]);
            }
            __syncthreads();
        }
    }

    // Epilogue
    const int mbase = m0 + ty * 8;
    const int nbase = n0 + tx * 4;

    float badd[4] = {0.f, 0.f, 0.f, 0.f};
    if (bias0) {
        #pragma unroll
        for (int j = 0; j < 4; ++j) badd[j] += bias0[nbase + j];
    }
    if (bias1) {
        #pragma unroll
        for (int j = 0; j < 4; ++j) badd[j] += bias1[nbase + j];
    }
    float wr[4] = {0.f, 0.f, 0.f, 0.f};
    if (intent) {
        #pragma unroll
        for (int j = 0; j < 4; ++j) wr[j] = wrow[nbase + j];
    }

    #pragma unroll
    for (int i = 0; i < 8; ++i) {
        const int m = mbase + i;
        float it = intent ? intent[m] : 0.f;
        float4 v;
        float vv[4];
        #pragma unroll
        for (int j = 0; j < 4; ++j) {
            float x = acc[i][j] + badd[j];
            if (intent) x = fmaf(it, wr[j], x);
            vv[j] = x;
        }
        if (Xadd) {
            float4 xa = *(const float4*)(Xadd + (size_t)m * ldc + nbase);
            vv[0] += xa.x; vv[1] += xa.y; vv[2] += xa.z; vv[3] += xa.w;
        }
        v.x = vv[0]; v.y = vv[1]; v.z = vv[2]; v.w = vv[3];
        *(float4*)(C + (size_t)m * ldc + nbase) = v;
    }
}

// ---------------------------------------------------------------------------
// LSTM cell elementwise: gates G[b, 0:4H] in (i,f,g,o) column blocks.
// ---------------------------------------------------------------------------
__device__ __forceinline__ float sigmoidf_(float x) {
    return 1.f / (1.f + expf(-x));
}

__global__ void lstm_cell_kernel(const float* __restrict__ G,
                                 float* __restrict__ h,
                                 float* __restrict__ c)
{
    int idx = blockIdx.x * blockDim.x + threadIdx.x;
    if (idx >= BB * HH) return;
    int b = idx >> 9;          // /512
    int j = idx & (HH - 1);
    const float* g = G + (size_t)b * N4H;
    float gi = g[j];
    float gf = g[j + HH];
    float gg = g[j + 2 * HH];
    float go = g[j + 3 * HH];
    float i_ = sigmoidf_(gi);
    float f_ = sigmoidf_(gf);
    float g_ = tanhf(gg);
    float o_ = sigmoidf_(go);
    float cn = fmaf(f_, c[idx], i_ * g_);
    float hn = o_ * tanhf(cn);
    c[idx] = cn;
    h[idx] = hn;
}

// ---------------------------------------------------------------------------
// Head: out[b*stride] = sigmoid( relu(h1[b,:]@W1 + b1) @ W2 + b2 )
// One warp per batch row; lane = column of the 32-wide hidden.
// ---------------------------------------------------------------------------
__global__ void head_kernel(const float* __restrict__ H1,
                            const float* __restrict__ W1,
                            const float* __restrict__ b1,
                            const float* __restrict__ W2,
                            const float* __restrict__ b2,
                            float* __restrict__ out, int out_stride,
                            float* __restrict__ intent_next)
{
    int gwarp = (blockIdx.x * blockDim.x + threadIdx.x) >> 5;
    int lane  = threadIdx.x & 31;
    if (gwarp >= BB) return;
    const float* h = H1 + (size_t)gwarp * HH;
    float acc = 0.f;
    #pragma unroll 8
    for (int k = 0; k < HH; ++k)
        acc = fmaf(__ldg(h + k), __ldg(W1 + k * 32 + lane), acc);
    acc += b1[lane];
    acc = fmaxf(acc, 0.f);
    float v = acc * W2[lane];
    #pragma unroll
    for (int off = 16; off; off >>= 1)
        v += __shfl_xor_sync(0xffffffffu, v, off);
    if (lane == 0) {
        float logit = v + b2[0];
        float it = 1.f / (1.f + expf(-logit));
        out[(size_t)gwarp * out_stride] = it;
        if (intent_next) intent_next[gwarp] = it;
    }
}

// ---------------------------------------------------------------------------
extern "C" void kernel_launch(void* const* d_in, const int* in_sizes, int n_in,
                              void* d_out, int out_size)
{
    const float* encoder = (const float*)d_in[0];
    const float* context = (const float*)d_in[1];
    const float* init_it = (const float*)d_in[2];
    const float* Wh_init = (const float*)d_in[3];
    const float* bh_init = (const float*)d_in[4];
    const float* Wc_init = (const float*)d_in[5];
    const float* bc_init = (const float*)d_in[6];
    const float* W_ih0   = (const float*)d_in[7];   // (257, 2048): row0=intent, rows1..256=context
    const float* W_hh0   = (const float*)d_in[8];   // (512, 2048)
    const float* b_ih0   = (const float*)d_in[9];
    const float* b_hh0   = (const float*)d_in[10];
    const float* W_ih1   = (const float*)d_in[11];  // (512, 2048)
    const float* W_hh1   = (const float*)d_in[12];  // (512, 2048)
    const float* b_ih1   = (const float*)d_in[13];
    const float* b_hh1   = (const float*)d_in[14];
    const float* Wo1     = (const float*)d_in[15];  // (512, 32)
    const float* bo1     = (const float*)d_in[16];
    const float* Wo2     = (const float*)d_in[17];  // (32, 1)
    const float* bo2     = (const float*)d_in[18];
    const float* Wg1     = (const float*)d_in[19];
    const float* bg1     = (const float*)d_in[20];
    const float* Wg2     = (const float*)d_in[21];
    const float* bg2     = (const float*)d_in[22];
    float* out = (float*)d_out;

    float *H0, *C0, *H1, *C1, *Xc, *G, *intent;
    cudaGetSymbolAddress((void**)&H0, g_H0);
    cudaGetSymbolAddress((void**)&C0, g_C0);
    cudaGetSymbolAddress((void**)&H1, g_H1);
    cudaGetSymbolAddress((void**)&C1, g_C1);
    cudaGetSymbolAddress((void**)&Xc, g_Xc);
    cudaGetSymbolAddress((void**)&G,  g_G);
    cudaGetSymbolAddress((void**)&intent, g_intent);

    dim3 blk(256);
    dim3 grid512(HH / BN, BB / BM);    // N=512
    dim3 grid2048(N4H / BN, BB / BM);  // N=2048
    const int cellBlocks = (BB * HH + 255) / 256;

    // ---- init: h0/h1/c0/c1 = encoder @ W*_init (+bias), split across L ----
    gemm_fused<<<grid512, blk>>>(encoder, DD, Wh_init, HH * 2, DD,
                                 nullptr, 0, nullptr, 0, 0,
                                 bh_init, nullptr, nullptr, nullptr, nullptr,
                                 H0, HH);
    gemm_fused<<<grid512, blk>>>(encoder, DD, Wh_init + HH, HH * 2, DD,
                                 nullptr, 0, nullptr, 0, 0,
                                 bh_init + HH, nullptr, nullptr, nullptr, nullptr,
                                 H1, HH);
    gemm_fused<<<grid512, blk>>>(encoder, DD, Wc_init, HH * 2, DD,
                                 nullptr, 0, nullptr, 0, 0,
                                 bc_init, nullptr, nullptr, nullptr, nullptr,
                                 C0, HH);
    gemm_fused<<<grid512, blk>>>(encoder, DD, Wc_init + HH, HH * 2, DD,
                                 nullptr, 0, nullptr, 0, 0,
                                 bc_init + HH, nullptr, nullptr, nullptr, nullptr,
                                 C1, HH);

    // ---- precompute Xc = context @ W_ih0[1:,:] + b_ih0 + b_hh0 (constant over T) ----
    gemm_fused<<<grid2048, blk>>>(context, DD, W_ih0 + N4H, N4H, DD,
                                  nullptr, 0, nullptr, 0, 0,
                                  b_ih0, b_hh0, nullptr, nullptr, nullptr,
                                  Xc, N4H);

    // ---- time loop ----
    for (int t = 0; t < TT; ++t) {
        const float* it = (t == 0) ? init_it : intent;

        // layer-0 gates: G = Xc + intent*W_ih0[0,:] + H0 @ W_hh0
        gemm_fused<<<grid2048, blk>>>(H0, HH, W_hh0, N4H, HH,
                                      nullptr, 0, nullptr, 0, 0,
                                      nullptr, nullptr, Xc, it, W_ih0,
                                      G, N4H);
        lstm_cell_kernel<<<cellBlocks, 256>>>(G, H0, C0);

        // layer-1 gates: G = H0n @ W_ih1 + H1 @ W_hh1 + b_ih1 + b_hh1
        gemm_fused<<<grid2048, blk>>>(H0, HH, W_ih1, N4H, HH,
                                      H1, HH, W_hh1, N4H, HH,
                                      b_ih1, b_hh1, nullptr, nullptr, nullptr,
                                      G, N4H);
        lstm_cell_kernel<<<cellBlocks, 256>>>(G, H1, C1);

        // per-step intent -> out[b*T + t], and feed next step
        head_kernel<<<BB / 8, 256>>>(H1, Wo1, bo1, Wo2, bo2,
                                     out + t, TT, intent);
    }

    // ---- global intent from final h1 -> out[B*T + b] ----
    head_kernel<<<BB / 8, 256>>>(H1, Wg1, bg1, Wg2, bg2,
                                 out + (size_t)BB * TT, 1, nullptr);
}

// round 4
// speedup vs baseline: 2.0319x; 2.0319x over previous
#include <cuda_runtime.h>
#include <cuda_bf16.h>
#include <math.h>
#include <stdint.h>

// Problem constants
#define BB 4096
#define DD 256
#define HH 512
#define TT 45
#define N4H 2048

// Tensor-core GEMM tile config
#define BMt 128
#define BNt 128
#define BKt 16
#define LDA_S 20     // As row stride (floats): conflict-free for frag loads
#define LDB_S 136    // Bs row stride (floats): 136%32==8 -> conflict-free

// Scratch (no allocations allowed -> __device__ globals)
__device__ float g_H0[BB * HH];
__device__ float g_C0[BB * HH];
__device__ float g_H1[BB * HH];
__device__ float g_C1[BB * HH];
__device__ float g_Xc[BB * N4H];
__device__ float g_G [BB * N4H];
__device__ float g_intent[BB];

// tf32 conversion: destination of cvt.rna.tf32.f32 is a b32 register.
__device__ __forceinline__ uint32_t to_tf32(float x) {
    uint32_t r;
    asm("cvt.rna.tf32.f32 %0, %1;" : "=r"(r) : "f"(x));
    return r;
}

__device__ __forceinline__ void mma_tf32(float c[4], uint32_t a0, uint32_t a1,
                                         uint32_t a2, uint32_t a3,
                                         uint32_t b0, uint32_t b1) {
    asm volatile(
        "mma.sync.aligned.m16n8k8.row.col.f32.tf32.tf32.f32 "
        "{%0,%1,%2,%3}, {%4,%5,%6,%7}, {%8,%9}, {%0,%1,%2,%3};\n"
        : "+f"(c[0]), "+f"(c[1]), "+f"(c[2]), "+f"(c[3])
        : "r"(a0), "r"(a1), "r"(a2), "r"(a3), "r"(b0), "r"(b1));
}

// ---------------------------------------------------------------------------
// Fused tf32 tensor-core GEMM:
// C[m,n] = sum_k A0[m,k]*B0[k,n] (+ sum_k A1[m,k]*B1[k,n])
//          + bias0[n] + bias1[n] + Xadd[m,n] + intent[m]*wrow[n]
// M % 128 == 0, N % 128 == 0, K % 16 == 0, pointers 16B aligned.
// ---------------------------------------------------------------------------
__global__ __launch_bounds__(256, 2)
void gemm_tf32(const float* __restrict__ A0, int lda0,
               const float* __restrict__ B0, int ldb0, int K0,
               const float* __restrict__ A1, int lda1,
               const float* __restrict__ B1, int ldb1, int K1,
               const float* __restrict__ bias0,
               const float* __restrict__ bias1,
               const float* __restrict__ Xadd,
               const float* __restrict__ intent,
               const float* __restrict__ wrow,
               float* __restrict__ C, int ldc)
{
    __shared__ uint32_t As[BMt * LDA_S];   // 128x16 (+pad) tf32 bits
    __shared__ uint32_t Bs[BKt * LDB_S];   // 16x128 (+pad) tf32 bits

    const int tid  = threadIdx.x;
    const int lane = tid & 31;
    const int wid  = tid >> 5;
    const int wm   = (wid & 1) * 64;    // warp m offset in block
    const int wn   = (wid >> 1) * 32;   // warp n offset in block
    const int g    = lane >> 2;         // group id 0..7
    const int t    = lane & 3;          // thread-in-group 0..3
    const int m0   = blockIdx.y * BMt;
    const int n0   = blockIdx.x * BNt;

    float acc[4][4][4];
    #pragma unroll
    for (int mi = 0; mi < 4; ++mi)
        #pragma unroll
        for (int ni = 0; ni < 4; ++ni)
            #pragma unroll
            for (int r = 0; r < 4; ++r) acc[mi][ni][r] = 0.f;

    // global loader indices
    const int arow = tid >> 1;          // 0..127
    const int acol = (tid & 1) * 8;     // 0 or 8
    const int brow = tid >> 4;          // 0..15
    const int bcol = (tid & 15) * 4;    // 0..60

    #pragma unroll 1
    for (int s = 0; s < 2; ++s) {
        const float* A = (s == 0) ? A0 : A1;
        if (A == nullptr) break;
        const float* Bp = (s == 0) ? B0 : B1;
        const int lda = (s == 0) ? lda0 : lda1;
        const int ldb = (s == 0) ? ldb0 : ldb1;
        const int K   = (s == 0) ? K0  : K1;
        const int ktiles = K / BKt;

        const float* Ag = A  + (size_t)(m0 + arow) * lda + acol;
        const float* Bg = Bp + (size_t)brow * ldb + n0 + bcol;

        float4 pa0, pa1, pb0, pb1;
        pa0 = *(const float4*)(Ag + 0);
        pa1 = *(const float4*)(Ag + 4);
        pb0 = *(const float4*)(Bg + 0);
        pb1 = *(const float4*)(Bg + 64);

        #pragma unroll 1
        for (int kt = 0; kt < ktiles; ++kt) {
            __syncthreads();
            // store prefetched tile to smem (convert to tf32 once here)
            {
                uint32_t* as = &As[arow * LDA_S + acol];
                as[0] = to_tf32(pa0.x); as[1] = to_tf32(pa0.y);
                as[2] = to_tf32(pa0.z); as[3] = to_tf32(pa0.w);
                as[4] = to_tf32(pa1.x); as[5] = to_tf32(pa1.y);
                as[6] = to_tf32(pa1.z); as[7] = to_tf32(pa1.w);
                uint32_t* bs = &Bs[brow * LDB_S + bcol];
                bs[0]  = to_tf32(pb0.x); bs[1]  = to_tf32(pb0.y);
                bs[2]  = to_tf32(pb0.z); bs[3]  = to_tf32(pb0.w);
                bs[64] = to_tf32(pb1.x); bs[65] = to_tf32(pb1.y);
                bs[66] = to_tf32(pb1.z); bs[67] = to_tf32(pb1.w);
            }
            __syncthreads();

            // prefetch next tile
            if (kt + 1 < ktiles) {
                const float* Agn = Ag + (kt + 1) * BKt;
                const float* Bgn = Bg + (size_t)(kt + 1) * BKt * ldb;
                pa0 = *(const float4*)(Agn + 0);
                pa1 = *(const float4*)(Agn + 4);
                pb0 = *(const float4*)(Bgn + 0);
                pb1 = *(const float4*)(Bgn + 64);
            }

            // compute: 2 k8 sub-steps
            #pragma unroll
            for (int kk = 0; kk < 2; ++kk) {
                const int kc = kk * 8;
                uint32_t afr[4][4];
                #pragma unroll
                for (int mi = 0; mi < 4; ++mi) {
                    const int r0 = wm + mi * 16 + g;
                    afr[mi][0] = As[r0 * LDA_S + kc + t];
                    afr[mi][1] = As[(r0 + 8) * LDA_S + kc + t];
                    afr[mi][2] = As[r0 * LDA_S + kc + t + 4];
                    afr[mi][3] = As[(r0 + 8) * LDA_S + kc + t + 4];
                }
                uint32_t bfr[4][2];
                #pragma unroll
                for (int ni = 0; ni < 4; ++ni) {
                    const int nc = wn + ni * 8 + g;
                    bfr[ni][0] = Bs[(kc + t) * LDB_S + nc];
                    bfr[ni][1] = Bs[(kc + t + 4) * LDB_S + nc];
                }
                #pragma unroll
                for (int mi = 0; mi < 4; ++mi)
                    #pragma unroll
                    for (int ni = 0; ni < 4; ++ni)
                        mma_tf32(acc[mi][ni],
                                 afr[mi][0], afr[mi][1], afr[mi][2], afr[mi][3],
                                 bfr[ni][0], bfr[ni][1]);
            }
        }
        __syncthreads();
    }

    // -------- epilogue --------
    #pragma unroll
    for (int mi = 0; mi < 4; ++mi) {
        const int row0 = m0 + wm + mi * 16 + g;
        const int row1 = row0 + 8;
        const float it0 = intent ? intent[row0] : 0.f;
        const float it1 = intent ? intent[row1] : 0.f;
        #pragma unroll
        for (int ni = 0; ni < 4; ++ni) {
            const int col = n0 + wn + ni * 8 + t * 2;
            float b0 = 0.f, b1 = 0.f;
            if (bias0) { b0 += bias0[col]; b1 += bias0[col + 1]; }
            if (bias1) { b0 += bias1[col]; b1 += bias1[col + 1]; }
            float w0 = 0.f, w1 = 0.f;
            if (intent) { w0 = wrow[col]; w1 = wrow[col + 1]; }

            float v00 = acc[mi][ni][0] + b0;
            float v01 = acc[mi][ni][1] + b1;
            float v10 = acc[mi][ni][2] + b0;
            float v11 = acc[mi][ni][3] + b1;
            if (intent) {
                v00 = fmaf(it0, w0, v00); v01 = fmaf(it0, w1, v01);
                v10 = fmaf(it1, w0, v10); v11 = fmaf(it1, w1, v11);
            }
            if (Xadd) {
                float2 x0 = *(const float2*)(Xadd + (size_t)row0 * ldc + col);
                float2 x1 = *(const float2*)(Xadd + (size_t)row1 * ldc + col);
                v00 += x0.x; v01 += x0.y;
                v10 += x1.x; v11 += x1.y;
            }
            *(float2*)(C + (size_t)row0 * ldc + col) = make_float2(v00, v01);
            *(float2*)(C + (size_t)row1 * ldc + col) = make_float2(v10, v11);
        }
    }
}

// ---------------------------------------------------------------------------
// LSTM cell elementwise: gates G[b, 0:4H] in (i,f,g,o) column blocks.
// ---------------------------------------------------------------------------
__device__ __forceinline__ float sigmoidf_(float x) {
    return 1.f / (1.f + expf(-x));
}

__global__ void lstm_cell_kernel(const float* __restrict__ G,
                                 float* __restrict__ h,
                                 float* __restrict__ c)
{
    int idx = blockIdx.x * blockDim.x + threadIdx.x;
    if (idx >= BB * HH) return;
    int b = idx >> 9;          // /512
    int j = idx & (HH - 1);
    const float* g = G + (size_t)b * N4H;
    float gi = g[j];
    float gf = g[j + HH];
    float gg = g[j + 2 * HH];
    float go = g[j + 3 * HH];
    float i_ = sigmoidf_(gi);
    float f_ = sigmoidf_(gf);
    float g_ = tanhf(gg);
    float o_ = sigmoidf_(go);
    float cn = fmaf(f_, c[idx], i_ * g_);
    float hn = o_ * tanhf(cn);
    c[idx] = cn;
    h[idx] = hn;
}

// ---------------------------------------------------------------------------
// Head: out[b*stride] = sigmoid( relu(h1[b,:]@W1 + b1) @ W2 + b2 )
// One warp per batch row; lane = column of the 32-wide hidden.
// ---------------------------------------------------------------------------
__global__ void head_kernel(const float* __restrict__ H1,
                            const float* __restrict__ W1,
                            const float* __restrict__ b1,
                            const float* __restrict__ W2,
                            const float* __restrict__ b2,
                            float* __restrict__ out, int out_stride,
                            float* __restrict__ intent_next)
{
    int gwarp = (blockIdx.x * blockDim.x + threadIdx.x) >> 5;
    int lane  = threadIdx.x & 31;
    if (gwarp >= BB) return;
    const float* h = H1 + (size_t)gwarp * HH;
    float acc = 0.f;
    #pragma unroll 8
    for (int k = 0; k < HH; ++k)
        acc = fmaf(__ldg(h + k), __ldg(W1 + k * 32 + lane), acc);
    acc += b1[lane];
    acc = fmaxf(acc, 0.f);
    float v = acc * W2[lane];
    #pragma unroll
    for (int off = 16; off; off >>= 1)
        v += __shfl_xor_sync(0xffffffffu, v, off);
    if (lane == 0) {
        float logit = v + b2[0];
        float it = 1.f / (1.f + expf(-logit));
        out[(size_t)gwarp * out_stride] = it;
        if (intent_next) intent_next[gwarp] = it;
    }
}

// ---------------------------------------------------------------------------
extern "C" void kernel_launch(void* const* d_in, const int* in_sizes, int n_in,
                              void* d_out, int out_size)
{
    const float* encoder = (const float*)d_in[0];
    const float* context = (const float*)d_in[1];
    const float* init_it = (const float*)d_in[2];
    const float* Wh_init = (const float*)d_in[3];
    const float* bh_init = (const float*)d_in[4];
    const float* Wc_init = (const float*)d_in[5];
    const float* bc_init = (const float*)d_in[6];
    const float* W_ih0   = (const float*)d_in[7];   // (257, 2048): row0=intent
    const float* W_hh0   = (const float*)d_in[8];   // (512, 2048)
    const float* b_ih0   = (const float*)d_in[9];
    const float* b_hh0   = (const float*)d_in[10];
    const float* W_ih1   = (const float*)d_in[11];  // (512, 2048)
    const float* W_hh1   = (const float*)d_in[12];  // (512, 2048)
    const float* b_ih1   = (const float*)d_in[13];
    const float* b_hh1   = (const float*)d_in[14];
    const float* Wo1     = (const float*)d_in[15];  // (512, 32)
    const float* bo1     = (const float*)d_in[16];
    const float* Wo2     = (const float*)d_in[17];  // (32, 1)
    const float* bo2     = (const float*)d_in[18];
    const float* Wg1     = (const float*)d_in[19];
    const float* bg1     = (const float*)d_in[20];
    const float* Wg2     = (const float*)d_in[21];
    const float* bg2     = (const float*)d_in[22];
    float* out = (float*)d_out;

    float *H0, *C0, *H1, *C1, *Xc, *G, *intent;
    cudaGetSymbolAddress((void**)&H0, g_H0);
    cudaGetSymbolAddress((void**)&C0, g_C0);
    cudaGetSymbolAddress((void**)&H1, g_H1);
    cudaGetSymbolAddress((void**)&C1, g_C1);
    cudaGetSymbolAddress((void**)&Xc, g_Xc);
    cudaGetSymbolAddress((void**)&G,  g_G);
    cudaGetSymbolAddress((void**)&intent, g_intent);

    dim3 blk(256);
    dim3 grid512(HH / BNt, BB / BMt);    // N=512  -> (4, 32)
    dim3 grid2048(N4H / BNt, BB / BMt);  // N=2048 -> (16, 32)
    const int cellBlocks = (BB * HH + 255) / 256;

    // ---- init: h0/h1/c0/c1 = encoder @ W*_init (+bias), split across L ----
    gemm_tf32<<<grid512, blk>>>(encoder, DD, Wh_init, HH * 2, DD,
                                nullptr, 0, nullptr, 0, 0,
                                bh_init, nullptr, nullptr, nullptr, nullptr,
                                H0, HH);
    gemm_tf32<<<grid512, blk>>>(encoder, DD, Wh_init + HH, HH * 2, DD,
                                nullptr, 0, nullptr, 0, 0,
                                bh_init + HH, nullptr, nullptr, nullptr, nullptr,
                                H1, HH);
    gemm_tf32<<<grid512, blk>>>(encoder, DD, Wc_init, HH * 2, DD,
                                nullptr, 0, nullptr, 0, 0,
                                bc_init, nullptr, nullptr, nullptr, nullptr,
                                C0, HH);
    gemm_tf32<<<grid512, blk>>>(encoder, DD, Wc_init + HH, HH * 2, DD,
                                nullptr, 0, nullptr, 0, 0,
                                bc_init + HH, nullptr, nullptr, nullptr, nullptr,
                                C1, HH);

    // ---- precompute Xc = context @ W_ih0[1:,:] + b_ih0 + b_hh0 ----
    gemm_tf32<<<grid2048, blk>>>(context, DD, W_ih0 + N4H, N4H, DD,
                                 nullptr, 0, nullptr, 0, 0,
                                 b_ih0, b_hh0, nullptr, nullptr, nullptr,
                                 Xc, N4H);

    // ---- time loop ----
    for (int t = 0; t < TT; ++t) {
        const float* it = (t == 0) ? init_it : intent;

        // layer-0 gates: G = Xc + intent*W_ih0[0,:] + H0 @ W_hh0
        gemm_tf32<<<grid2048, blk>>>(H0, HH, W_hh0, N4H, HH,
                                     nullptr, 0, nullptr, 0, 0,
                                     nullptr, nullptr, Xc, it, W_ih0,
                                     G, N4H);
        lstm_cell_kernel<<<cellBlocks, 256>>>(G, H0, C0);

        // layer-1 gates: G = H0n @ W_ih1 + H1 @ W_hh1 + b_ih1 + b_hh1
        gemm_tf32<<<grid2048, blk>>>(H0, HH, W_ih1, N4H, HH,
                                     H1, HH, W_hh1, N4H, HH,
                                     b_ih1, b_hh1, nullptr, nullptr, nullptr,
                                     G, N4H);
        lstm_cell_kernel<<<cellBlocks, 256>>>(G, H1, C1);

        // per-step intent -> out[b*T + t], and feed next step
        head_kernel<<<BB / 8, 256>>>(H1, Wo1, bo1, Wo2, bo2,
                                     out + t, TT, intent);
    }

    // ---- global intent from final h1 -> out[B*T + b] ----
    head_kernel<<<BB / 8, 256>>>(H1, Wg1, bg1, Wg2, bg2,
                                 out + (size_t)BB * TT, 1, nullptr);
}

// round 5
// speedup vs baseline: 3.7564x; 1.8487x over previous
#include <cuda_runtime.h>
#include <cuda_bf16.h>
#include <math.h>
#include <stdint.h>

// Problem constants
#define BB 4096
#define DD 256
#define HH 512
#define TT 45
#define N4H 2048

// Tensor-core GEMM tile config (bf16, m16n8k16)
#define BMt 128
#define BNt 128
#define BKt 32
#define LDA_H 40     // As row stride in halfs (80B = 5*16B -> conflict-free ldmatrix)
#define LDB_H 136    // Bs row stride in halfs (272B = 17*16B -> conflict-free)

// fp32 scratch
__device__ float g_H1f[BB * HH];
__device__ float g_C0[BB * HH];
__device__ float g_C1[BB * HH];
__device__ float g_Xc[BB * N4H];
__device__ float g_G [BB * N4H];
__device__ float g_intent[BB];
__device__ float g_dummy[BB * HH];

// bf16 scratch
__device__ __nv_bfloat16 g_bEnc [BB * DD];
__device__ __nv_bfloat16 g_bCtx [BB * DD];
__device__ __nv_bfloat16 g_bWh  [DD * 2 * HH];
__device__ __nv_bfloat16 g_bWc  [DD * 2 * HH];
__device__ __nv_bfloat16 g_bWi0c[DD * N4H];     // W_ih0 rows 1..256 (context part)
__device__ __nv_bfloat16 g_bWhh0[HH * N4H];
__device__ __nv_bfloat16 g_bWih1[HH * N4H];
__device__ __nv_bfloat16 g_bWhh1[HH * N4H];
__device__ __nv_bfloat16 g_bH0  [BB * HH];
__device__ __nv_bfloat16 g_bH1  [BB * HH];

// ---------------------------------------------------------------------------
__device__ __forceinline__ void cp16(uint32_t dst_sh, const void* src) {
    asm volatile("cp.async.cg.shared.global [%0], [%1], 16;\n"
                 :: "r"(dst_sh), "l"(src));
}
#define CP_COMMIT() asm volatile("cp.async.commit_group;\n" ::: "memory")
template <int N>
__device__ __forceinline__ void cp_wait() {
    asm volatile("cp.async.wait_group %0;\n" :: "n"(N) : "memory");
}

__device__ __forceinline__ void ldm_x4(uint32_t r[4], uint32_t addr) {
    asm volatile("ldmatrix.sync.aligned.m8n8.x4.shared.b16 {%0,%1,%2,%3}, [%4];\n"
                 : "=r"(r[0]), "=r"(r[1]), "=r"(r[2]), "=r"(r[3]) : "r"(addr));
}
__device__ __forceinline__ void ldm_x4t(uint32_t r[4], uint32_t addr) {
    asm volatile("ldmatrix.sync.aligned.m8n8.x4.trans.shared.b16 {%0,%1,%2,%3}, [%4];\n"
                 : "=r"(r[0]), "=r"(r[1]), "=r"(r[2]), "=r"(r[3]) : "r"(addr));
}
__device__ __forceinline__ void mma_bf16(float c[4], const uint32_t a[4],
                                         uint32_t b0, uint32_t b1) {
    asm volatile(
        "mma.sync.aligned.m16n8k16.row.col.f32.bf16.bf16.f32 "
        "{%0,%1,%2,%3}, {%4,%5,%6,%7}, {%8,%9}, {%0,%1,%2,%3};\n"
        : "+f"(c[0]), "+f"(c[1]), "+f"(c[2]), "+f"(c[3])
        : "r"(a[0]), "r"(a[1]), "r"(a[2]), "r"(a[3]), "r"(b0), "r"(b1));
}

// ---------------------------------------------------------------------------
// Fused bf16 tensor-core GEMM:
// C[m,n] = sum_k A0[m,k]*B0[k,n] (+ sum_k A1[m,k]*B1[k,n])
//          + bias0[n] + bias1[n] + Xadd[m,n] + intent[m]*wrow[n]
// Optional bf16 copy of C into Cb. M%128==0, N%128==0, K%32==0.
// ---------------------------------------------------------------------------
__global__ __launch_bounds__(256, 2)
void gemm_bf16(const __nv_bfloat16* __restrict__ A0, int lda0,
               const __nv_bfloat16* __restrict__ B0, int ldb0, int K0,
               const __nv_bfloat16* __restrict__ A1, int lda1,
               const __nv_bfloat16* __restrict__ B1, int ldb1, int K1,
               const float* __restrict__ bias0,
               const float* __restrict__ bias1,
               const float* __restrict__ Xadd,
               const float* __restrict__ intent,
               const float* __restrict__ wrow,
               float* __restrict__ C, int ldc,
               __nv_bfloat16* __restrict__ Cb)
{
    __shared__ __nv_bfloat16 As[2][BMt * LDA_H];
    __shared__ __nv_bfloat16 Bs[2][BKt * LDB_H];

    const int tid  = threadIdx.x;
    const int lane = tid & 31;
    const int wid  = tid >> 5;
    const int wm   = (wid & 1) * 64;
    const int wn   = (wid >> 1) * 32;
    const int g    = lane >> 2;
    const int t    = lane & 3;
    const int m0   = blockIdx.y * BMt;
    const int n0   = blockIdx.x * BNt;

    const uint32_t as_base = (uint32_t)__cvta_generic_to_shared(&As[0][0]);
    const uint32_t bs_base = (uint32_t)__cvta_generic_to_shared(&Bs[0][0]);
    const uint32_t as_sz = BMt * LDA_H * 2;
    const uint32_t bs_sz = BKt * LDB_H * 2;

    float acc[4][4][4];
    #pragma unroll
    for (int mi = 0; mi < 4; ++mi)
        #pragma unroll
        for (int ni = 0; ni < 4; ++ni)
            #pragma unroll
            for (int r = 0; r < 4; ++r) acc[mi][ni][r] = 0.f;

    // loader indices
    const int arow = tid >> 1;           // 0..127
    const int aoff = (tid & 1) * 16;     // halfs
    const int brow = tid >> 4;           // 0..15 (and +16)
    const int boff = (tid & 15) * 8;     // halfs

    const int kt0    = K0 / BKt;
    const int ktotal = kt0 + (A1 ? K1 / BKt : 0);

    // stage issue
    auto issue = [&](int kt, int b) {
        const __nv_bfloat16* Aop; const __nv_bfloat16* Bop;
        int lda, ldb, kl;
        if (kt < kt0) { Aop = A0; Bop = B0; lda = lda0; ldb = ldb0; kl = kt; }
        else          { Aop = A1; Bop = B1; lda = lda1; ldb = ldb1; kl = kt - kt0; }
        const __nv_bfloat16* asrc = Aop + (size_t)(m0 + arow) * lda + kl * BKt + aoff;
        uint32_t adst = as_base + b * as_sz + (arow * LDA_H + aoff) * 2;
        cp16(adst, asrc);
        cp16(adst + 16, asrc + 8);
        const __nv_bfloat16* bsrc = Bop + (size_t)(kl * BKt + brow) * ldb + n0 + boff;
        uint32_t bdst = bs_base + b * bs_sz + (brow * LDB_H + boff) * 2;
        cp16(bdst, bsrc);
        cp16(bdst + 16 * LDB_H * 2, bsrc + (size_t)16 * ldb);
    };

    issue(0, 0);
    CP_COMMIT();

    // fragment smem addresses (vary only with buffer & kstep)
    const int a_lrow = lane & 15;
    const int a_lcol = (lane >> 4) << 3;
    const int b_lrow = (lane & 7) + (lane & 8);
    const int b_lcol = (lane >> 4) << 3;

    #pragma unroll 1
    for (int kt = 0; kt < ktotal; ++kt) {
        if (kt + 1 < ktotal) {
            issue(kt + 1, (kt + 1) & 1);
            CP_COMMIT();
            cp_wait<1>();
        } else {
            cp_wait<0>();
        }
        __syncthreads();

        const int b = kt & 1;
        const uint32_t asb = as_base + b * as_sz;
        const uint32_t bsb = bs_base + b * bs_sz;

        #pragma unroll
        for (int kk = 0; kk < 2; ++kk) {
            const int kc = kk * 16;
            uint32_t afr[4][4];
            #pragma unroll
            for (int mi = 0; mi < 4; ++mi) {
                uint32_t addr = asb +
                    ((wm + mi * 16 + a_lrow) * LDA_H + kc + a_lcol) * 2;
                ldm_x4(afr[mi], addr);
            }
            uint32_t bfr[4][2];
            #pragma unroll
            for (int nj = 0; nj < 2; ++nj) {
                uint32_t r[4];
                uint32_t addr = bsb +
                    ((kc + b_lrow) * LDB_H + wn + nj * 16 + b_lcol) * 2;
                ldm_x4t(r, addr);
                bfr[nj * 2 + 0][0] = r[0]; bfr[nj * 2 + 0][1] = r[1];
                bfr[nj * 2 + 1][0] = r[2]; bfr[nj * 2 + 1][1] = r[3];
            }
            #pragma unroll
            for (int mi = 0; mi < 4; ++mi)
                #pragma unroll
                for (int ni = 0; ni < 4; ++ni)
                    mma_bf16(acc[mi][ni], afr[mi], bfr[ni][0], bfr[ni][1]);
        }
        __syncthreads();
    }

    // -------- epilogue --------
    #pragma unroll
    for (int mi = 0; mi < 4; ++mi) {
        const int row0 = m0 + wm + mi * 16 + g;
        const int row1 = row0 + 8;
        const float it0 = intent ? intent[row0] : 0.f;
        const float it1 = intent ? intent[row1] : 0.f;
        #pragma unroll
        for (int ni = 0; ni < 4; ++ni) {
            const int col = n0 + wn + ni * 8 + t * 2;
            float b0 = 0.f, b1 = 0.f;
            if (bias0) { b0 += bias0[col]; b1 += bias0[col + 1]; }
            if (bias1) { b0 += bias1[col]; b1 += bias1[col + 1]; }
            float w0 = 0.f, w1 = 0.f;
            if (intent) { w0 = wrow[col]; w1 = wrow[col + 1]; }

            float v00 = acc[mi][ni][0] + b0;
            float v01 = acc[mi][ni][1] + b1;
            float v10 = acc[mi][ni][2] + b0;
            float v11 = acc[mi][ni][3] + b1;
            if (intent) {
                v00 = fmaf(it0, w0, v00); v01 = fmaf(it0, w1, v01);
                v10 = fmaf(it1, w0, v10); v11 = fmaf(it1, w1, v11);
            }
            if (Xadd) {
                float2 x0 = *(const float2*)(Xadd + (size_t)row0 * ldc + col);
                float2 x1 = *(const float2*)(Xadd + (size_t)row1 * ldc + col);
                v00 += x0.x; v01 += x0.y;
                v10 += x1.x; v11 += x1.y;
            }
            *(float2*)(C + (size_t)row0 * ldc + col) = make_float2(v00, v01);
            *(float2*)(C + (size_t)row1 * ldc + col) = make_float2(v10, v11);
            if (Cb) {
                *(__nv_bfloat162*)(Cb + (size_t)row0 * ldc + col) =
                    __nv_bfloat162(__float2bfloat16(v00), __float2bfloat16(v01));
                *(__nv_bfloat162*)(Cb + (size_t)row1 * ldc + col) =
                    __nv_bfloat162(__float2bfloat16(v10), __float2bfloat16(v11));
            }
        }
    }
}

// ---------------------------------------------------------------------------
// fp32 -> bf16 conversion
// ---------------------------------------------------------------------------
__global__ void cvt_bf16_kernel(const float* __restrict__ src,
                                __nv_bfloat16* __restrict__ dst, int n)
{
    int i = blockIdx.x * blockDim.x + threadIdx.x;
    int stride = gridDim.x * blockDim.x;
    for (; i < n; i += stride) dst[i] = __float2bfloat16(src[i]);
}

// ---------------------------------------------------------------------------
// LSTM cell elementwise
// ---------------------------------------------------------------------------
__device__ __forceinline__ float sigmoidf_(float x) {
    return 1.f / (1.f + expf(-x));
}

__global__ void lstm_cell_kernel(const float* __restrict__ G,
                                 float* __restrict__ hf,          // nullable
                                 __nv_bfloat16* __restrict__ hb,
                                 float* __restrict__ c)
{
    int idx = blockIdx.x * blockDim.x + threadIdx.x;
    if (idx >= BB * HH) return;
    int b = idx >> 9;
    int j = idx & (HH - 1);
    const float* gp = G + (size_t)b * N4H;
    float gi = gp[j];
    float gf = gp[j + HH];
    float gg = gp[j + 2 * HH];
    float go = gp[j + 3 * HH];
    float i_ = sigmoidf_(gi);
    float f_ = sigmoidf_(gf);
    float g_ = tanhf(gg);
    float o_ = sigmoidf_(go);
    float cn = fmaf(f_, c[idx], i_ * g_);
    float hn = o_ * tanhf(cn);
    c[idx] = cn;
    hb[idx] = __float2bfloat16(hn);
    if (hf) hf[idx] = hn;
}

// ---------------------------------------------------------------------------
// Head: out[b*stride] = sigmoid( relu(h1[b,:]@W1 + b1) @ W2 + b2 )
// ---------------------------------------------------------------------------
__global__ void head_kernel(const float* __restrict__ H1,
                            const float* __restrict__ W1,
                            const float* __restrict__ b1,
                            const float* __restrict__ W2,
                            const float* __restrict__ b2,
                            float* __restrict__ out, int out_stride,
                            float* __restrict__ intent_next)
{
    int gwarp = (blockIdx.x * blockDim.x + threadIdx.x) >> 5;
    int lane  = threadIdx.x & 31;
    if (gwarp >= BB) return;
    const float* h = H1 + (size_t)gwarp * HH;
    float acc = 0.f;
    #pragma unroll 8
    for (int k = 0; k < HH; ++k)
        acc = fmaf(__ldg(h + k), __ldg(W1 + k * 32 + lane), acc);
    acc += b1[lane];
    acc = fmaxf(acc, 0.f);
    float v = acc * W2[lane];
    #pragma unroll
    for (int off = 16; off; off >>= 1)
        v += __shfl_xor_sync(0xffffffffu, v, off);
    if (lane == 0) {
        float logit = v + b2[0];
        float it = 1.f / (1.f + expf(-logit));
        out[(size_t)gwarp * out_stride] = it;
        if (intent_next) intent_next[gwarp] = it;
    }
}

// ---------------------------------------------------------------------------
extern "C" void kernel_launch(void* const* d_in, const int* in_sizes, int n_in,
                              void* d_out, int out_size)
{
    const float* encoder = (const float*)d_in[0];
    const float* context = (const float*)d_in[1];
    const float* init_it = (const float*)d_in[2];
    const float* Wh_init = (const float*)d_in[3];
    const float* bh_init = (const float*)d_in[4];
    const float* Wc_init = (const float*)d_in[5];
    const float* bc_init = (const float*)d_in[6];
    const float* W_ih0   = (const float*)d_in[7];   // (257, 2048): row0=intent
    const float* W_hh0   = (const float*)d_in[8];
    const float* b_ih0   = (const float*)d_in[9];
    const float* b_hh0   = (const float*)d_in[10];
    const float* W_ih1   = (const float*)d_in[11];
    const float* W_hh1   = (const float*)d_in[12];
    const float* b_ih1   = (const float*)d_in[13];
    const float* b_hh1   = (const float*)d_in[14];
    const float* Wo1     = (const float*)d_in[15];
    const float* bo1     = (const float*)d_in[16];
    const float* Wo2     = (const float*)d_in[17];
    const float* bo2     = (const float*)d_in[18];
    const float* Wg1     = (const float*)d_in[19];
    const float* bg1     = (const float*)d_in[20];
    const float* Wg2     = (const float*)d_in[21];
    const float* bg2     = (const float*)d_in[22];
    float* out = (float*)d_out;

    float *H1f, *C0, *C1, *Xc, *G, *intent, *dummy;
    cudaGetSymbolAddress((void**)&H1f, g_H1f);
    cudaGetSymbolAddress((void**)&C0,  g_C0);
    cudaGetSymbolAddress((void**)&C1,  g_C1);
    cudaGetSymbolAddress((void**)&Xc,  g_Xc);
    cudaGetSymbolAddress((void**)&G,   g_G);
    cudaGetSymbolAddress((void**)&intent, g_intent);
    cudaGetSymbolAddress((void**)&dummy,  g_dummy);

    __nv_bfloat16 *bEnc, *bCtx, *bWh, *bWc, *bWi0c, *bWhh0, *bWih1, *bWhh1, *bH0, *bH1;
    cudaGetSymbolAddress((void**)&bEnc,  g_bEnc);
    cudaGetSymbolAddress((void**)&bCtx,  g_bCtx);
    cudaGetSymbolAddress((void**)&bWh,   g_bWh);
    cudaGetSymbolAddress((void**)&bWc,   g_bWc);
    cudaGetSymbolAddress((void**)&bWi0c, g_bWi0c);
    cudaGetSymbolAddress((void**)&bWhh0, g_bWhh0);
    cudaGetSymbolAddress((void**)&bWih1, g_bWih1);
    cudaGetSymbolAddress((void**)&bWhh1, g_bWhh1);
    cudaGetSymbolAddress((void**)&bH0,   g_bH0);
    cudaGetSymbolAddress((void**)&bH1,   g_bH1);

    // ---- fp32 -> bf16 conversions ----
    auto cvt = [&](const float* s, __nv_bfloat16* d, int n) {
        cvt_bf16_kernel<<<(n + 255) / 256 < 1024 ? (n + 255) / 256 : 1024, 256>>>(s, d, n);
    };
    cvt(encoder, bEnc, BB * DD);
    cvt(context, bCtx, BB * DD);
    cvt(Wh_init, bWh, DD * 2 * HH);
    cvt(Wc_init, bWc, DD * 2 * HH);
    cvt(W_ih0 + N4H, bWi0c, DD * N4H);
    cvt(W_hh0, bWhh0, HH * N4H);
    cvt(W_ih1, bWih1, HH * N4H);
    cvt(W_hh1, bWhh1, HH * N4H);

    dim3 blk(256);
    dim3 grid512(HH / BNt, BB / BMt);
    dim3 grid2048(N4H / BNt, BB / BMt);
    const int cellBlocks = (BB * HH + 255) / 256;

    // ---- init states ----
    gemm_bf16<<<grid512, blk>>>(bEnc, DD, bWh, 2 * HH, DD,
                                nullptr, 0, nullptr, 0, 0,
                                bh_init, nullptr, nullptr, nullptr, nullptr,
                                dummy, HH, bH0);
    gemm_bf16<<<grid512, blk>>>(bEnc, DD, bWh + HH, 2 * HH, DD,
                                nullptr, 0, nullptr, 0, 0,
                                bh_init + HH, nullptr, nullptr, nullptr, nullptr,
                                dummy, HH, bH1);
    gemm_bf16<<<grid512, blk>>>(bEnc, DD, bWc, 2 * HH, DD,
                                nullptr, 0, nullptr, 0, 0,
                                bc_init, nullptr, nullptr, nullptr, nullptr,
                                C0, HH, nullptr);
    gemm_bf16<<<grid512, blk>>>(bEnc, DD, bWc + HH, 2 * HH, DD,
                                nullptr, 0, nullptr, 0, 0,
                                bc_init + HH, nullptr, nullptr, nullptr, nullptr,
                                C1, HH, nullptr);

    // ---- Xc = context @ W_ih0[1:,:] + b_ih0 + b_hh0 ----
    gemm_bf16<<<grid2048, blk>>>(bCtx, DD, bWi0c, N4H, DD,
                                 nullptr, 0, nullptr, 0, 0,
                                 b_ih0, b_hh0, nullptr, nullptr, nullptr,
                                 Xc, N4H, nullptr);

    // ---- time loop ----
    for (int t = 0; t < TT; ++t) {
        const float* it = (t == 0) ? init_it : intent;

        gemm_bf16<<<grid2048, blk>>>(bH0, HH, bWhh0, N4H, HH,
                                     nullptr, 0, nullptr, 0, 0,
                                     nullptr, nullptr, Xc, it, W_ih0,
                                     G, N4H, nullptr);
        lstm_cell_kernel<<<cellBlocks, 256>>>(G, nullptr, bH0, C0);

        gemm_bf16<<<grid2048, blk>>>(bH0, HH, bWih1, N4H, HH,
                                     bH1, HH, bWhh1, N4H, HH,
                                     b_ih1, b_hh1, nullptr, nullptr, nullptr,
                                     G, N4H, nullptr);
        lstm_cell_kernel<<<cellBlocks, 256>>>(G, H1f, bH1, C1);

        head_kernel<<<BB / 8, 256>>>(H1f, Wo1, bo1, Wo2, bo2,
                                     out + t, TT, intent);
    }

    head_kernel<<<BB / 8, 256>>>(H1f, Wg1, bg1, Wg2, bg2,
                                 out + (size_t)BB * TT, 1, nullptr);
}